// round 15
// baseline (speedup 1.0000x reference)
#include <cuda_runtime.h>
#include <cuda_fp16.h>
#include <math_constants.h>
#include <cstdint>

// Problem constants
#define BB 4
#define CC 256
#define NN 4096
#define NG 8
#define CPG 32
#define EPSV 1e-5f
#define ATTN_SCALE 0.0625f  // 1/sqrt(256), folded into Wq/bq

// 1-pass gemm smem geometry (2 tiles, double buffered)
#define GROW 40
#define MATB (128 * GROW * 2)     // 10240
#define BUF2 (2 * MATB)           // 20480
#define GEMM_SMEM (2 * BUF2)      // 40960

// flash smem geometry (64-query CTA, 32-key tiles, 2 CTAs/SM)
#define FQ_STRIDE 264             // 528B rows (256 fp16 + pad)
#define FV_STRIDE 40              // 80B rows (32 fp16 + pad)
#define FQ0 0
#define FK0 33792                 // 64*528
#define FK1 50688                 // +32*528
#define FV0 67584                 // +32*528
#define FV1 88064                 // +256*80
#define FLASH_SMEM 108544         // +256*80

// ---------------- static scratch ----------------
__device__ __align__(16) float g_part[512 * 2];              // GN partial sums
__device__ float g_mean[BB * NG];
__device__ float g_inv[BB * NG];
__device__ __align__(16) __half g_ht[BB * NN * CC];          // h^T [b][n][c] fp16
__device__ __align__(16) __half g_wqk[2 * CC * CC];          // concat(Wq*scale, Wk)
__device__ __align__(16) __half g_wv[CC * CC];
__device__ __align__(16) __half g_wo[CC * CC];
__device__ __align__(16) float g_bqk[2 * CC];                // concat(bq*scale, bk)
__device__ __align__(16) __half g_qk16[BB * NN * 2 * CC];    // qk^T [b][n][512]
__device__ __align__(16) __half g_v16[BB * CC * NN];         // v [b][o][m]
__device__ __align__(16) __half g_ot16[BB * NN * CC];        // Ot [b][n][c]

// ================= PTX helpers =================
__device__ __forceinline__ uint32_t smem_u32(const void* p) {
    uint32_t a;
    asm("{ .reg .u64 t; cvta.to.shared.u64 t, %1; cvt.u32.u64 %0, t; }" : "=r"(a) : "l"(p));
    return a;
}
__device__ __forceinline__ void ldm4(uint32_t r[4], uint32_t addr) {
    asm volatile("ldmatrix.sync.aligned.m8n8.x4.shared.b16 {%0,%1,%2,%3}, [%4];"
                 : "=r"(r[0]), "=r"(r[1]), "=r"(r[2]), "=r"(r[3]) : "r"(addr));
}
__device__ __forceinline__ void mma16816h(float c[4], const uint32_t a[4],
                                          uint32_t b0, uint32_t b1) {
    asm volatile("mma.sync.aligned.m16n8k16.row.col.f32.f16.f16.f32 "
                 "{%0,%1,%2,%3}, {%4,%5,%6,%7}, {%8,%9}, {%0,%1,%2,%3};"
                 : "+f"(c[0]), "+f"(c[1]), "+f"(c[2]), "+f"(c[3])
                 : "r"(a[0]), "r"(a[1]), "r"(a[2]), "r"(a[3]), "r"(b0), "r"(b1));
}
__device__ __forceinline__ void cpa16(uint32_t dst, const void* src) {
    asm volatile("cp.async.cg.shared.global [%0], [%1], 16;" :: "r"(dst), "l"(src));
}
#define CPA_COMMIT() asm volatile("cp.async.commit_group;" ::: "memory")
#define CPA_WAIT0()  asm volatile("cp.async.wait_group 0;" ::: "memory")
#define CPA_WAIT1()  asm volatile("cp.async.wait_group 1;" ::: "memory")

__device__ __forceinline__ uint32_t pack_h2(float a, float b) {
    __half2 h;
    h.x = __float2half_rn(a);
    h.y = __float2half_rn(b);
    return *(uint32_t*)&h;
}

// ---------------- GroupNorm stage 1 ----------------
__global__ void gnstat1_kernel(const float* __restrict__ x) {
    const int bg = blockIdx.y;
    const int chunk = blockIdx.x;
    const float* xp = x + (size_t)bg * (CPG * NN) + chunk * 8192;
    float s = 0.f, ss = 0.f;
    for (int i = threadIdx.x; i < 2048; i += 256) {
        float4 v = ((const float4*)xp)[i];
        s += v.x + v.y + v.z + v.w;
        ss += v.x * v.x + v.y * v.y + v.z * v.z + v.w * v.w;
    }
    __shared__ float rs[256], rq[256];
    rs[threadIdx.x] = s; rq[threadIdx.x] = ss;
    __syncthreads();
    for (int st = 128; st > 0; st >>= 1) {
        if (threadIdx.x < st) { rs[threadIdx.x] += rs[threadIdx.x + st]; rq[threadIdx.x] += rq[threadIdx.x + st]; }
        __syncthreads();
    }
    if (threadIdx.x == 0) {
        g_part[(bg * 16 + chunk) * 2 + 0] = rs[0];
        g_part[(bg * 16 + chunk) * 2 + 1] = rq[0];
    }
}

// ---------------- GroupNorm stage 2 ----------------
__global__ void gnstat2_kernel() {
    const int i = threadIdx.x;
    float s = 0.f, ss = 0.f;
    #pragma unroll
    for (int j = 0; j < 16; j++) {
        s += g_part[(i * 16 + j) * 2 + 0];
        ss += g_part[(i * 16 + j) * 2 + 1];
    }
    const float Mf = (float)(CPG * NN);
    const float mean = s / Mf;
    const float var = ss / Mf - mean * mean;
    g_mean[i] = mean;
    g_inv[i] = rsqrtf(var + EPSV);
}

// ---------------- all weight converts + bias concat (scale folded into Q) ----------------
__global__ void wsplitall_kernel(const float* __restrict__ Wq, const float* __restrict__ Wk,
                                 const float* __restrict__ Wv, const float* __restrict__ Wo,
                                 const float* __restrict__ bq, const float* __restrict__ bk) {
    const int i = blockIdx.x * blockDim.x + threadIdx.x;
    if (i < CC * CC) {
        g_wqk[i] = __float2half_rn(Wq[i] * ATTN_SCALE);
        g_wqk[CC * CC + i] = __float2half_rn(Wk[i]);
        g_wv[i] = __float2half_rn(Wv[i]);
        g_wo[i] = __float2half_rn(Wo[i]);
        if (i < CC) g_bqk[i] = bq[i] * ATTN_SCALE;
        else if (i < 2 * CC) g_bqk[i] = bk[i - CC];
    }
}

// ---------------- fused GN-apply + transpose + fp16 ----------------
__global__ void tconv_kernel(const float* __restrict__ x,
                             const float* __restrict__ sc,
                             const float* __restrict__ bi,
                             __half* __restrict__ dst) {
    __shared__ float t[32][33];
    const int b = blockIdx.z;
    const int n0 = blockIdx.x * 32;
    const int c0 = blockIdx.y * 32;
    const int tx = threadIdx.x, ty = threadIdx.y;  // (32, 8)
    const int bg = b * NG + blockIdx.y;
    const float mean = g_mean[bg];
    const float inv = g_inv[bg];
    const float* s = x + (size_t)b * CC * NN;
    #pragma unroll
    for (int k = 0; k < 4; k++)
        t[ty + 8 * k][tx] = s[(size_t)(c0 + ty + 8 * k) * NN + n0 + tx];
    __syncthreads();
    const int c = c0 + tx;
    const float a = inv * sc[c];
    const float d = bi[c] - mean * a;
    const size_t base = (size_t)b * NN * CC;
    #pragma unroll
    for (int k = 0; k < 4; k++) {
        const int n = n0 + ty + 8 * k;
        dst[base + (size_t)n * CC + c] = __float2half_rn(t[tx][ty + 8 * k] * a + d);
    }
}

// ============================================================================
// 1-pass fp16 GEMM (unchanged)
// ============================================================================
template<int OUTMODE, int BIASMODE, bool DO_RES>
__global__ __launch_bounds__(256, 1)
void gemm1h_kernel(const __half* __restrict__ Ah, const __half* __restrict__ Bh,
                   size_t ldA, size_t ldB, size_t strA, size_t strB,
                   float* __restrict__ OutF, __half* __restrict__ Oh,
                   size_t ldOut, size_t strOut,
                   const float* __restrict__ bias, const float* __restrict__ res,
                   int K, float scale) {
    extern __shared__ char smem[];
    const uint32_t sb = smem_u32(smem);
    const int tid = threadIdx.x;
    const int lane = tid & 31, wid = tid >> 5;
    const int warpM = wid & 3, warpN = wid >> 2;
    const int bz = blockIdx.z;
    const int N0 = blockIdx.x * 128;
    const int M0 = blockIdx.y * 128;

    const __half* pA = Ah + (size_t)bz * strA + (size_t)M0 * ldA;
    const __half* pB = Bh + (size_t)bz * strB + (size_t)N0 * ldB;

    const int ga = lane >> 3;
    const int arow = ((ga & 1) << 3) + (lane & 7);
    const int akoff = (ga >> 1) << 3;
    const int brow = ((ga >> 1) << 3) + (lane & 7);
    const int bkoff = (ga & 1) << 3;

    float acc[2][8][4];
    #pragma unroll
    for (int i = 0; i < 2; i++)
        #pragma unroll
        for (int j = 0; j < 8; j++)
            #pragma unroll
            for (int k = 0; k < 4; k++) acc[i][j][k] = 0.f;

    const int nch = K >> 5;

    #define ISSUE_COPY2(bufi, kc) do {                                             \
        _Pragma("unroll")                                                          \
        for (int i_ = 0; i_ < 4; i_++) {                                           \
            int idx_ = tid + i_ * 256;                                             \
            int mat_ = idx_ >> 9;                                                  \
            int r_ = (idx_ >> 2) & 127;                                            \
            int seg_ = idx_ & 3;                                                   \
            const __half* src_ = (mat_ ? pB + (size_t)r_ * ldB : pA + (size_t)r_ * ldA) \
                                 + (kc) + seg_ * 8;                                \
            uint32_t dst_ = sb + (bufi) * BUF2 + mat_ * MATB + (r_ * GROW + seg_ * 8) * 2; \
            cpa16(dst_, src_);                                                     \
        }                                                                          \
        CPA_COMMIT();                                                              \
    } while (0)

    ISSUE_COPY2(0, 0);

    for (int c = 0; c < nch; c++) {
        if (c + 1 < nch) {
            ISSUE_COPY2((c + 1) & 1, (c + 1) << 5);
            CPA_WAIT1();
        } else {
            CPA_WAIT0();
        }
        __syncthreads();

        const uint32_t bufb = sb + (c & 1) * BUF2;
        #pragma unroll
        for (int ks = 0; ks < 32; ks += 16) {
            uint32_t ah[2][4];
            #pragma unroll
            for (int mt = 0; mt < 2; mt++) {
                uint32_t off = (uint32_t)(((warpM * 32 + mt * 16 + arow) * GROW + ks + akoff) * 2);
                ldm4(ah[mt], bufb + off);
            }
            uint32_t bh[4][4];
            #pragma unroll
            for (int ng = 0; ng < 4; ng++) {
                uint32_t off = (uint32_t)(((warpN * 64 + ng * 16 + brow) * GROW + ks + bkoff) * 2);
                ldm4(bh[ng], bufb + MATB + off);
            }
            #pragma unroll
            for (int mt = 0; mt < 2; mt++)
                #pragma unroll
                for (int ng = 0; ng < 4; ng++)
                    #pragma unroll
                    for (int h = 0; h < 2; h++)
                        mma16816h(acc[mt][ng * 2 + h], ah[mt], bh[ng][h * 2], bh[ng][h * 2 + 1]);
        }
        __syncthreads();
    }

    #pragma unroll
    for (int mt = 0; mt < 2; mt++)
        #pragma unroll
        for (int nt = 0; nt < 8; nt++) {
            const int row0 = M0 + warpM * 32 + mt * 16 + (lane >> 2);
            const int col = N0 + warpN * 64 + nt * 8 + ((lane & 3) << 1);
            #pragma unroll
            for (int rr = 0; rr < 2; rr++) {
                const int r = row0 + rr * 8;
                float v0 = acc[mt][nt][rr * 2 + 0] * scale;
                float v1 = acc[mt][nt][rr * 2 + 1] * scale;
                if (BIASMODE == 1) { const float bb = bias[r]; v0 += bb; v1 += bb; }
                if (BIASMODE == 2) { v0 += bias[col]; v1 += bias[col + 1]; }
                const size_t off = (size_t)bz * strOut + (size_t)r * ldOut + col;
                if (DO_RES) { v0 += res[off]; v1 += res[off + 1]; }
                if (OUTMODE == 0) {
                    float2 o; o.x = v0; o.y = v1;
                    *(float2*)&OutF[off] = o;
                } else {
                    __half2 hp;
                    hp.x = __float2half_rn(v0);
                    hp.y = __float2half_rn(v1);
                    *(__half2*)&Oh[off] = hp;
                }
            }
        }
}

// ============================================================================
// Flash attention: 64-query CTAs (128 thr, 4 warps x 16 rows), 32-key tiles,
// 2 CTAs/SM for inter-CTA overlap. Pipelined S (body does PV(it) + S(it+1)).
// Max-free softmax, scale pre-folded into Q. 128 iterations.
// ============================================================================
__global__ __launch_bounds__(128, 2)
void flash_kernel(const __half* __restrict__ QK, const __half* __restrict__ Vh,
                  __half* __restrict__ Ot) {
    extern __shared__ char smem[];
    const uint32_t sb = smem_u32(smem);
    const int tid = threadIdx.x;
    const int lane = tid & 31, wid = tid >> 5;
    const int b = blockIdx.y;
    const int n0 = blockIdx.x * 64;

    const __half* qh = QK + (size_t)b * NN * 512;
    const __half* kh = qh + 256;
    const __half* vh = Vh + (size_t)b * CC * NN;
    const size_t boN = (size_t)b * NN * CC;

    const uint32_t fkb[2] = { sb + FK0, sb + FK1 };
    const uint32_t fvb[2] = { sb + FV0, sb + FV1 };

    // K tile: 32 rows x 256c  (8 cpa16/thread)
    #define LOAD_K(bufi, mm0) do {                                                 \
        for (int i = tid; i < 1024; i += 128) {                                    \
            const int r_ = i >> 5, seg_ = i & 31;                                  \
            cpa16(fkb[bufi] + r_ * 528 + seg_ * 16,                                \
                  kh + (size_t)((mm0) + r_) * 512 + seg_ * 8);                     \
        }                                                                          \
    } while (0)
    // V tile: 256 rows x 32m  (8 cpa16/thread)
    #define LOAD_V(bufi, mm0) do {                                                 \
        for (int i = tid; i < 1024; i += 128) {                                    \
            const int r_ = i >> 2, seg_ = i & 3;                                   \
            cpa16(fvb[bufi] + r_ * 80 + seg_ * 16,                                 \
                  vh + (size_t)r_ * NN + (mm0) + seg_ * 8);                        \
        }                                                                          \
    } while (0)

    // prologue group 0: Q (64 rows) + K(0)
    for (int i = tid; i < 2048; i += 128) {
        const int r = i >> 5, seg = i & 31;
        cpa16(sb + FQ0 + r * 528 + seg * 16, qh + (size_t)(n0 + r) * 512 + seg * 8);
    }
    LOAD_K(0, 0);
    CPA_COMMIT();
    // prologue group 1: K(1) + V(0)
    LOAD_K(1, 32);
    LOAD_V(0, 0);
    CPA_COMMIT();

    const int ga = lane >> 3;
    const int arow = ((ga & 1) << 3) + (lane & 7);
    const int akoff = (ga >> 1) << 3;
    const int brow = ((ga >> 1) << 3) + (lane & 7);
    const int bkoff = (ga & 1) << 3;

    float o[32][4];
    #pragma unroll
    for (int i = 0; i < 32; i++)
        #pragma unroll
        for (int j = 0; j < 4; j++) o[i][j] = 0.f;
    float li0 = 0.f, li1 = 0.f;
    float sa[4][4], sbuf[4][4];

    const uint32_t qbase = sb + FQ0 + (uint32_t)((wid * 16 + arow) * FQ_STRIDE + akoff) * 2;

    CPA_WAIT0();
    __syncthreads();

    // ---- prologue: S(0) into sa (reads Kbuf[0]) ----
    #pragma unroll
    for (int t = 0; t < 4; t++)
        #pragma unroll
        for (int e = 0; e < 4; e++) sa[t][e] = 0.f;
    #pragma unroll
    for (int ks = 0; ks < 256; ks += 16) {
        uint32_t qf[4];
        ldm4(qf, qbase + ks * 2);
        #pragma unroll
        for (int g = 0; g < 2; g++) {
            uint32_t kf[4];
            ldm4(kf, fkb[0] + (uint32_t)((g * 16 + brow) * FQ_STRIDE + ks + bkoff) * 2);
            mma16816h(sa[g * 2 + 0], qf, kf[0], kf[1]);
            mma16816h(sa[g * 2 + 1], qf, kf[2], kf[3]);
        }
    }

    // body: PV(it) from scur, S(it+1) into snxt (interleaved per 16-key chunk)
    #define FLASH_BODY(scur, snxt, it, DO_S) do {                                  \
        CPA_WAIT0();                                                               \
        __syncthreads();                                                           \
        if ((it) + 2 < 128) LOAD_K((it) & 1, ((it) + 2) * 32);                     \
        if ((it) + 1 < 128) LOAD_V(((it) + 1) & 1, ((it) + 1) * 32);               \
        CPA_COMMIT();                                                              \
        const uint32_t vbase_ = fvb[(it) & 1];                                     \
        const uint32_t kbase_ = fkb[((it) + 1) & 1];                               \
        if (DO_S) {                                                                \
            _Pragma("unroll")                                                      \
            for (int t_ = 0; t_ < 4; t_++)                                         \
                _Pragma("unroll")                                                  \
                for (int e_ = 0; e_ < 4; e_++) snxt[t_][e_] = 0.f;                 \
        }                                                                          \
        _Pragma("unroll")                                                          \
        for (int kt = 0; kt < 2; kt++) {                                           \
            const int t0_ = kt * 2, t1_ = t0_ + 1;                                 \
            const float e00 = __expf(scur[t0_][0]);                                \
            const float e01 = __expf(scur[t0_][1]);                                \
            const float e02 = __expf(scur[t0_][2]);                                \
            const float e03 = __expf(scur[t0_][3]);                                \
            const float e10 = __expf(scur[t1_][0]);                                \
            const float e11 = __expf(scur[t1_][1]);                                \
            const float e12 = __expf(scur[t1_][2]);                                \
            const float e13 = __expf(scur[t1_][3]);                                \
            li0 += e00 + e01 + e10 + e11;                                          \
            li1 += e02 + e03 + e12 + e13;                                          \
            uint32_t pah[4];                                                       \
            pah[0] = pack_h2(e00, e01);                                            \
            pah[1] = pack_h2(e02, e03);                                            \
            pah[2] = pack_h2(e10, e11);                                            \
            pah[3] = pack_h2(e12, e13);                                            \
            _Pragma("unroll")                                                      \
            for (int cg = 0; cg < 16; cg++) {                                      \
                uint32_t vf[4];                                                    \
                ldm4(vf, vbase_ + (uint32_t)((cg * 16 + brow) * FV_STRIDE + bkoff) * 2 + kt * 32); \
                mma16816h(o[cg * 2 + 0], pah, vf[0], vf[1]);                       \
                mma16816h(o[cg * 2 + 1], pah, vf[2], vf[3]);                       \
            }                                                                      \
            if (DO_S) {                                                            \
                _Pragma("unroll")                                                  \
                for (int ks2 = 0; ks2 < 8; ks2++) {                                \
                    const int ks_ = (kt * 8 + ks2) * 16;                           \
                    uint32_t qf[4];                                                \
                    ldm4(qf, qbase + ks_ * 2);                                     \
                    _Pragma("unroll")                                              \
                    for (int g_ = 0; g_ < 2; g_++) {                               \
                        uint32_t kf[4];                                            \
                        ldm4(kf, kbase_ + (uint32_t)((g_ * 16 + brow) * FQ_STRIDE + ks_ + bkoff) * 2); \
                        mma16816h(snxt[g_ * 2 + 0], qf, kf[0], kf[1]);             \
                        mma16816h(snxt[g_ * 2 + 1], qf, kf[2], kf[3]);             \
                    }                                                              \
                }                                                                  \
            }                                                                      \
        }                                                                          \
    } while (0)

    #pragma unroll 1
    for (int it2 = 0; it2 < 126; it2 += 2) {
        FLASH_BODY(sa, sbuf, it2, true);
        FLASH_BODY(sbuf, sa, it2 + 1, true);
    }
    FLASH_BODY(sa, sbuf, 126, true);      // PV(126), S(127) -> sbuf
    FLASH_BODY(sbuf, sa, 127, false);     // PV(127) only

    // quad-reduce l, normalize, write Ot fp16
    li0 += __shfl_xor_sync(0xffffffffu, li0, 1);
    li0 += __shfl_xor_sync(0xffffffffu, li0, 2);
    li1 += __shfl_xor_sync(0xffffffffu, li1, 1);
    li1 += __shfl_xor_sync(0xffffffffu, li1, 2);
    const float inv0 = 1.f / li0;
    const float inv1 = 1.f / li1;

    const int r0 = n0 + wid * 16 + (lane >> 2);
    #pragma unroll
    for (int ct = 0; ct < 32; ct++) {
        const int col = ct * 8 + ((lane & 3) << 1);
        __half2 a0, a1;
        a0.x = __float2half_rn(o[ct][0] * inv0);
        a0.y = __float2half_rn(o[ct][1] * inv0);
        a1.x = __float2half_rn(o[ct][2] * inv1);
        a1.y = __float2half_rn(o[ct][3] * inv1);
        *(__half2*)&Ot[boN + (size_t)r0 * CC + col] = a0;
        *(__half2*)&Ot[boN + (size_t)(r0 + 8) * CC + col] = a1;
    }
}

// ---------------- launch ----------------
extern "C" void kernel_launch(void* const* d_in, const int* in_sizes, int n_in,
                              void* d_out, int out_size) {
    const float* input = (const float*)d_in[0];
    const float* gns   = (const float*)d_in[1];
    const float* gnb   = (const float*)d_in[2];
    const float* Wq    = (const float*)d_in[3];
    const float* bq    = (const float*)d_in[4];
    const float* Wk    = (const float*)d_in[5];
    const float* bk    = (const float*)d_in[6];
    const float* Wv    = (const float*)d_in[7];
    const float* bv    = (const float*)d_in[8];
    const float* Wo    = (const float*)d_in[9];
    const float* bo    = (const float*)d_in[10];
    float* out = (float*)d_out;

    __half *hth, *wqk, *wv, *wo, *qk16, *v16, *ot16;
    float* bqk;
    cudaGetSymbolAddress((void**)&hth, g_ht);
    cudaGetSymbolAddress((void**)&wqk, g_wqk);
    cudaGetSymbolAddress((void**)&wv, g_wv);
    cudaGetSymbolAddress((void**)&wo, g_wo);
    cudaGetSymbolAddress((void**)&bqk, g_bqk);
    cudaGetSymbolAddress((void**)&qk16, g_qk16);
    cudaGetSymbolAddress((void**)&v16, g_v16);
    cudaGetSymbolAddress((void**)&ot16, g_ot16);

    cudaFuncSetAttribute(gemm1h_kernel<1, 2, false>, cudaFuncAttributeMaxDynamicSharedMemorySize, GEMM_SMEM);
    cudaFuncSetAttribute(gemm1h_kernel<1, 1, false>, cudaFuncAttributeMaxDynamicSharedMemorySize, GEMM_SMEM);
    cudaFuncSetAttribute(gemm1h_kernel<0, 1, true>, cudaFuncAttributeMaxDynamicSharedMemorySize, GEMM_SMEM);
    cudaFuncSetAttribute(flash_kernel, cudaFuncAttributeMaxDynamicSharedMemorySize, FLASH_SMEM);

    // 1) GroupNorm stats + all weight converts (one kernel)
    gnstat1_kernel<<<dim3(16, 32), 256>>>(input);
    wsplitall_kernel<<<256, 256>>>(Wq, Wk, Wv, Wo, bq, bk);
    gnstat2_kernel<<<1, 32>>>();

    // 2) fused GN-apply + transpose -> fp16
    dim3 gt(NN / 32, CC / 32, BB);
    tconv_kernel<<<gt, dim3(32, 8)>>>(input, gns, gnb, hth);

    // 3) QK merged projection: qk[b][n][512] = hT . [Wq*s;Wk]^T + [bq*s;bk]
    dim3 gqk(2 * CC / 128, NN / 128, BB);
    gemm1h_kernel<1, 2, false><<<gqk, 256, GEMM_SMEM>>>(
        hth, wqk,
        CC, CC, (size_t)NN * CC, 0,
        nullptr, qk16, 2 * CC, (size_t)NN * 2 * CC, bqk, nullptr, CC, 1.0f);
    //    V projection: v[b][o][m]
    dim3 gv(NN / 128, CC / 128, BB);
    gemm1h_kernel<1, 1, false><<<gv, 256, GEMM_SMEM>>>(
        wv, hth,
        CC, CC, 0, (size_t)NN * CC,
        nullptr, v16, NN, (size_t)CC * NN, bv, nullptr, CC, 1.0f);

    // 4) flash attention (64-query CTAs, 2/SM) -> Ot fp16
    dim3 gfl(NN / 64, BB);
    flash_kernel<<<gfl, 128, FLASH_SMEM>>>(qk16, v16, ot16);

    // 5) final: out = Wo . Ot^T + bo + residual (fp32 out)
    dim3 gf(NN / 128, CC / 128, BB);
    gemm1h_kernel<0, 1, true><<<gf, 256, GEMM_SMEM>>>(
        wo, ot16,
        CC, CC, 0, (size_t)NN * CC,
        out, nullptr, NN, (size_t)CC * NN, bo, input, CC, 1.0f);
}

// round 16
// speedup vs baseline: 1.1802x; 1.1802x over previous
#include <cuda_runtime.h>
#include <cuda_fp16.h>
#include <math_constants.h>
#include <cstdint>

// Problem constants
#define BB 4
#define CC 256
#define NN 4096
#define NG 8
#define CPG 32
#define EPSV 1e-5f
#define ATTN_SCALE 0.0625f  // 1/sqrt(256), folded into Wq/bq

// 1-pass gemm smem geometry (2 tiles, double buffered)
#define GROW 40
#define MATB (128 * GROW * 2)     // 10240
#define BUF2 (2 * MATB)           // 20480
#define GEMM_SMEM (2 * BUF2)      // 40960

// flash smem geometry (R14 config: 128-query CTA, 64-key tiles)
#define FQ_STRIDE 264             // 528B rows (256 fp16 + pad)
#define FV_STRIDE 72              // 144B rows (64 fp16 + pad)
#define FQ0 0
#define FK0 67584                 // 128*528
#define FK1 (FK0 + 33792)         // 64*528
#define FV0 (FK1 + 33792)         // 135168
#define FV1 (FV0 + 36864)         // 256*144
#define FLASH_SMEM (FV1 + 36864)  // 208896

// ---------------- static scratch ----------------
__device__ __align__(16) float g_part[512 * 2];              // GN partial sums
__device__ float g_mean[BB * NG];
__device__ float g_inv[BB * NG];
__device__ __align__(16) __half g_ht[BB * NN * CC];          // h^T [b][n][c] fp16
__device__ __align__(16) __half g_wqk[2 * CC * CC];          // concat(Wq*scale, Wk)
__device__ __align__(16) __half g_wv[CC * CC];
__device__ __align__(16) __half g_wo[CC * CC];
__device__ __align__(16) float g_bqk[2 * CC];                // concat(bq*scale, bk)
__device__ __align__(16) __half g_qk16[BB * NN * 2 * CC];    // qk^T [b][n][512]
__device__ __align__(16) __half g_v16[BB * CC * NN];         // v [b][o][m]
__device__ __align__(16) __half g_ot16[BB * NN * CC];        // Ot [b][n][c]

// ================= PTX helpers =================
__device__ __forceinline__ uint32_t smem_u32(const void* p) {
    uint32_t a;
    asm("{ .reg .u64 t; cvta.to.shared.u64 t, %1; cvt.u32.u64 %0, t; }" : "=r"(a) : "l"(p));
    return a;
}
__device__ __forceinline__ void ldm4(uint32_t r[4], uint32_t addr) {
    asm volatile("ldmatrix.sync.aligned.m8n8.x4.shared.b16 {%0,%1,%2,%3}, [%4];"
                 : "=r"(r[0]), "=r"(r[1]), "=r"(r[2]), "=r"(r[3]) : "r"(addr));
}
__device__ __forceinline__ void mma16816h(float c[4], const uint32_t a[4],
                                          uint32_t b0, uint32_t b1) {
    asm volatile("mma.sync.aligned.m16n8k16.row.col.f32.f16.f16.f32 "
                 "{%0,%1,%2,%3}, {%4,%5,%6,%7}, {%8,%9}, {%0,%1,%2,%3};"
                 : "+f"(c[0]), "+f"(c[1]), "+f"(c[2]), "+f"(c[3])
                 : "r"(a[0]), "r"(a[1]), "r"(a[2]), "r"(a[3]), "r"(b0), "r"(b1));
}
__device__ __forceinline__ void cpa16(uint32_t dst, const void* src) {
    asm volatile("cp.async.cg.shared.global [%0], [%1], 16;" :: "r"(dst), "l"(src));
}
#define CPA_COMMIT() asm volatile("cp.async.commit_group;" ::: "memory")
#define CPA_WAIT0()  asm volatile("cp.async.wait_group 0;" ::: "memory")
#define CPA_WAIT1()  asm volatile("cp.async.wait_group 1;" ::: "memory")

__device__ __forceinline__ uint32_t pack_h2(float a, float b) {
    __half2 h;
    h.x = __float2half_rn(a);
    h.y = __float2half_rn(b);
    return *(uint32_t*)&h;
}

// ---------------- GroupNorm stage 1 ----------------
__global__ void gnstat1_kernel(const float* __restrict__ x) {
    const int bg = blockIdx.y;
    const int chunk = blockIdx.x;
    const float* xp = x + (size_t)bg * (CPG * NN) + chunk * 8192;
    float s = 0.f, ss = 0.f;
    for (int i = threadIdx.x; i < 2048; i += 256) {
        float4 v = ((const float4*)xp)[i];
        s += v.x + v.y + v.z + v.w;
        ss += v.x * v.x + v.y * v.y + v.z * v.z + v.w * v.w;
    }
    __shared__ float rs[256], rq[256];
    rs[threadIdx.x] = s; rq[threadIdx.x] = ss;
    __syncthreads();
    for (int st = 128; st > 0; st >>= 1) {
        if (threadIdx.x < st) { rs[threadIdx.x] += rs[threadIdx.x + st]; rq[threadIdx.x] += rq[threadIdx.x + st]; }
        __syncthreads();
    }
    if (threadIdx.x == 0) {
        g_part[(bg * 16 + chunk) * 2 + 0] = rs[0];
        g_part[(bg * 16 + chunk) * 2 + 1] = rq[0];
    }
}

// ---------------- GroupNorm stage 2 ----------------
__global__ void gnstat2_kernel() {
    const int i = threadIdx.x;
    float s = 0.f, ss = 0.f;
    #pragma unroll
    for (int j = 0; j < 16; j++) {
        s += g_part[(i * 16 + j) * 2 + 0];
        ss += g_part[(i * 16 + j) * 2 + 1];
    }
    const float Mf = (float)(CPG * NN);
    const float mean = s / Mf;
    const float var = ss / Mf - mean * mean;
    g_mean[i] = mean;
    g_inv[i] = rsqrtf(var + EPSV);
}

// ---------------- all weight converts + bias concat (scale folded into Q) ----------------
__global__ void wsplitall_kernel(const float* __restrict__ Wq, const float* __restrict__ Wk,
                                 const float* __restrict__ Wv, const float* __restrict__ Wo,
                                 const float* __restrict__ bq, const float* __restrict__ bk) {
    const int i = blockIdx.x * blockDim.x + threadIdx.x;
    if (i < CC * CC) {
        g_wqk[i] = __float2half_rn(Wq[i] * ATTN_SCALE);
        g_wqk[CC * CC + i] = __float2half_rn(Wk[i]);
        g_wv[i] = __float2half_rn(Wv[i]);
        g_wo[i] = __float2half_rn(Wo[i]);
        if (i < CC) g_bqk[i] = bq[i] * ATTN_SCALE;
        else if (i < 2 * CC) g_bqk[i] = bk[i - CC];
    }
}

// ---------------- fused GN-apply + transpose + fp16 ----------------
__global__ void tconv_kernel(const float* __restrict__ x,
                             const float* __restrict__ sc,
                             const float* __restrict__ bi,
                             __half* __restrict__ dst) {
    __shared__ float t[32][33];
    const int b = blockIdx.z;
    const int n0 = blockIdx.x * 32;
    const int c0 = blockIdx.y * 32;
    const int tx = threadIdx.x, ty = threadIdx.y;  // (32, 8)
    const int bg = b * NG + blockIdx.y;
    const float mean = g_mean[bg];
    const float inv = g_inv[bg];
    const float* s = x + (size_t)b * CC * NN;
    #pragma unroll
    for (int k = 0; k < 4; k++)
        t[ty + 8 * k][tx] = s[(size_t)(c0 + ty + 8 * k) * NN + n0 + tx];
    __syncthreads();
    const int c = c0 + tx;
    const float a = inv * sc[c];
    const float d = bi[c] - mean * a;
    const size_t base = (size_t)b * NN * CC;
    #pragma unroll
    for (int k = 0; k < 4; k++) {
        const int n = n0 + ty + 8 * k;
        dst[base + (size_t)n * CC + c] = __float2half_rn(t[tx][ty + 8 * k] * a + d);
    }
}

// ============================================================================
// 1-pass fp16 GEMM, now 2 CTAs/SM for better wave packing
// ============================================================================
template<int OUTMODE, int BIASMODE, bool DO_RES>
__global__ __launch_bounds__(256, 2)
void gemm1h_kernel(const __half* __restrict__ Ah, const __half* __restrict__ Bh,
                   size_t ldA, size_t ldB, size_t strA, size_t strB,
                   float* __restrict__ OutF, __half* __restrict__ Oh,
                   size_t ldOut, size_t strOut,
                   const float* __restrict__ bias, const float* __restrict__ res,
                   int K, float scale) {
    extern __shared__ char smem[];
    const uint32_t sb = smem_u32(smem);
    const int tid = threadIdx.x;
    const int lane = tid & 31, wid = tid >> 5;
    const int warpM = wid & 3, warpN = wid >> 2;
    const int bz = blockIdx.z;
    const int N0 = blockIdx.x * 128;
    const int M0 = blockIdx.y * 128;

    const __half* pA = Ah + (size_t)bz * strA + (size_t)M0 * ldA;
    const __half* pB = Bh + (size_t)bz * strB + (size_t)N0 * ldB;

    const int ga = lane >> 3;
    const int arow = ((ga & 1) << 3) + (lane & 7);
    const int akoff = (ga >> 1) << 3;
    const int brow = ((ga >> 1) << 3) + (lane & 7);
    const int bkoff = (ga & 1) << 3;

    float acc[2][8][4];
    #pragma unroll
    for (int i = 0; i < 2; i++)
        #pragma unroll
        for (int j = 0; j < 8; j++)
            #pragma unroll
            for (int k = 0; k < 4; k++) acc[i][j][k] = 0.f;

    const int nch = K >> 5;

    #define ISSUE_COPY2(bufi, kc) do {                                             \
        _Pragma("unroll")                                                          \
        for (int i_ = 0; i_ < 4; i_++) {                                           \
            int idx_ = tid + i_ * 256;                                             \
            int mat_ = idx_ >> 9;                                                  \
            int r_ = (idx_ >> 2) & 127;                                            \
            int seg_ = idx_ & 3;                                                   \
            const __half* src_ = (mat_ ? pB + (size_t)r_ * ldB : pA + (size_t)r_ * ldA) \
                                 + (kc) + seg_ * 8;                                \
            uint32_t dst_ = sb + (bufi) * BUF2 + mat_ * MATB + (r_ * GROW + seg_ * 8) * 2; \
            cpa16(dst_, src_);                                                     \
        }                                                                          \
        CPA_COMMIT();                                                              \
    } while (0)

    ISSUE_COPY2(0, 0);

    for (int c = 0; c < nch; c++) {
        if (c + 1 < nch) {
            ISSUE_COPY2((c + 1) & 1, (c + 1) << 5);
            CPA_WAIT1();
        } else {
            CPA_WAIT0();
        }
        __syncthreads();

        const uint32_t bufb = sb + (c & 1) * BUF2;
        #pragma unroll
        for (int ks = 0; ks < 32; ks += 16) {
            uint32_t ah[2][4];
            #pragma unroll
            for (int mt = 0; mt < 2; mt++) {
                uint32_t off = (uint32_t)(((warpM * 32 + mt * 16 + arow) * GROW + ks + akoff) * 2);
                ldm4(ah[mt], bufb + off);
            }
            uint32_t bh[4][4];
            #pragma unroll
            for (int ng = 0; ng < 4; ng++) {
                uint32_t off = (uint32_t)(((warpN * 64 + ng * 16 + brow) * GROW + ks + bkoff) * 2);
                ldm4(bh[ng], bufb + MATB + off);
            }
            #pragma unroll
            for (int mt = 0; mt < 2; mt++)
                #pragma unroll
                for (int ng = 0; ng < 4; ng++)
                    #pragma unroll
                    for (int h = 0; h < 2; h++)
                        mma16816h(acc[mt][ng * 2 + h], ah[mt], bh[ng][h * 2], bh[ng][h * 2 + 1]);
        }
        __syncthreads();
    }

    #pragma unroll
    for (int mt = 0; mt < 2; mt++)
        #pragma unroll
        for (int nt = 0; nt < 8; nt++) {
            const int row0 = M0 + warpM * 32 + mt * 16 + (lane >> 2);
            const int col = N0 + warpN * 64 + nt * 8 + ((lane & 3) << 1);
            #pragma unroll
            for (int rr = 0; rr < 2; rr++) {
                const int r = row0 + rr * 8;
                float v0 = acc[mt][nt][rr * 2 + 0] * scale;
                float v1 = acc[mt][nt][rr * 2 + 1] * scale;
                if (BIASMODE == 1) { const float bb = bias[r]; v0 += bb; v1 += bb; }
                if (BIASMODE == 2) { v0 += bias[col]; v1 += bias[col + 1]; }
                const size_t off = (size_t)bz * strOut + (size_t)r * ldOut + col;
                if (DO_RES) { v0 += res[off]; v1 += res[off + 1]; }
                if (OUTMODE == 0) {
                    float2 o; o.x = v0; o.y = v1;
                    *(float2*)&OutF[off] = o;
                } else {
                    __half2 hp;
                    hp.x = __float2half_rn(v0);
                    hp.y = __float2half_rn(v1);
                    *(__half2*)&Oh[off] = hp;
                }
            }
        }
}

// ============================================================================
// Flash attention (R14 config): 128-query CTA, 8 warps x 16 rows, 64-key
// tiles, pipelined S (body: PV(it) + S(it+1) interleaved). Max-free softmax.
// ============================================================================
__global__ __launch_bounds__(256, 1)
void flash_kernel(const __half* __restrict__ QK, const __half* __restrict__ Vh,
                  __half* __restrict__ Ot) {
    extern __shared__ char smem[];
    const uint32_t sb = smem_u32(smem);
    const int tid = threadIdx.x;
    const int lane = tid & 31, wid = tid >> 5;
    const int b = blockIdx.y;
    const int n0 = blockIdx.x * 128;

    const __half* qh = QK + (size_t)b * NN * 512;
    const __half* kh = qh + 256;
    const __half* vh = Vh + (size_t)b * CC * NN;
    const size_t boN = (size_t)b * NN * CC;

    const uint32_t fkb[2] = { sb + FK0, sb + FK1 };
    const uint32_t fvb[2] = { sb + FV0, sb + FV1 };

    #define LOAD_K(bufi, mm0) do {                                                 \
        for (int i = tid; i < 2048; i += 256) {                                    \
            const int r_ = i >> 5, seg_ = i & 31;                                  \
            cpa16(fkb[bufi] + r_ * 528 + seg_ * 16,                                \
                  kh + (size_t)((mm0) + r_) * 512 + seg_ * 8);                     \
        }                                                                          \
    } while (0)
    #define LOAD_V(bufi, mm0) do {                                                 \
        for (int i = tid; i < 2048; i += 256) {                                    \
            const int r_ = i >> 3, seg_ = i & 7;                                   \
            cpa16(fvb[bufi] + r_ * 144 + seg_ * 16,                                \
                  vh + (size_t)r_ * NN + (mm0) + seg_ * 8);                        \
        }                                                                          \
    } while (0)

    // prologue group 0: Q + K(0)
    for (int i = tid; i < 128 * 32; i += 256) {
        const int r = i >> 5, seg = i & 31;
        cpa16(sb + FQ0 + r * 528 + seg * 16, qh + (size_t)(n0 + r) * 512 + seg * 8);
    }
    LOAD_K(0, 0);
    CPA_COMMIT();
    // prologue group 1: K(1) + V(0)
    LOAD_K(1, 64);
    LOAD_V(0, 0);
    CPA_COMMIT();

    const int ga = lane >> 3;
    const int arow = ((ga & 1) << 3) + (lane & 7);
    const int akoff = (ga >> 1) << 3;
    const int brow = ((ga >> 1) << 3) + (lane & 7);
    const int bkoff = (ga & 1) << 3;

    float o[32][4];
    #pragma unroll
    for (int i = 0; i < 32; i++)
        #pragma unroll
        for (int j = 0; j < 4; j++) o[i][j] = 0.f;
    float li0 = 0.f, li1 = 0.f;
    float sa[8][4], sbuf[8][4];

    const uint32_t qbase = sb + FQ0 + (uint32_t)((wid * 16 + arow) * FQ_STRIDE + akoff) * 2;

    CPA_WAIT0();
    __syncthreads();

    // ---- prologue: S(0) into sa (reads Kbuf[0]) ----
    #pragma unroll
    for (int t = 0; t < 8; t++)
        #pragma unroll
        for (int e = 0; e < 4; e++) sa[t][e] = 0.f;
    #pragma unroll
    for (int ks = 0; ks < 256; ks += 16) {
        uint32_t qf[4];
        ldm4(qf, qbase + ks * 2);
        #pragma unroll
        for (int g = 0; g < 4; g++) {
            uint32_t kf[4];
            ldm4(kf, fkb[0] + (uint32_t)((g * 16 + brow) * FQ_STRIDE + ks + bkoff) * 2);
            mma16816h(sa[g * 2 + 0], qf, kf[0], kf[1]);
            mma16816h(sa[g * 2 + 1], qf, kf[2], kf[3]);
        }
    }

    #define FLASH_BODY(scur, snxt, it, DO_S) do {                                  \
        CPA_WAIT0();                                                               \
        __syncthreads();                                                           \
        if ((it) + 2 < 64) LOAD_K((it) & 1, ((it) + 2) * 64);                      \
        if ((it) + 1 < 64) LOAD_V(((it) + 1) & 1, ((it) + 1) * 64);                \
        CPA_COMMIT();                                                              \
        const uint32_t vbase_ = fvb[(it) & 1];                                     \
        const uint32_t kbase_ = fkb[((it) + 1) & 1];                               \
        if (DO_S) {                                                                \
            _Pragma("unroll")                                                      \
            for (int t_ = 0; t_ < 8; t_++)                                         \
                _Pragma("unroll")                                                  \
                for (int e_ = 0; e_ < 4; e_++) snxt[t_][e_] = 0.f;                 \
        }                                                                          \
        _Pragma("unroll")                                                          \
        for (int kt = 0; kt < 4; kt++) {                                           \
            const int t0_ = kt * 2, t1_ = t0_ + 1;                                 \
            const float e00 = __expf(scur[t0_][0]);                                \
            const float e01 = __expf(scur[t0_][1]);                                \
            const float e02 = __expf(scur[t0_][2]);                                \
            const float e03 = __expf(scur[t0_][3]);                                \
            const float e10 = __expf(scur[t1_][0]);                                \
            const float e11 = __expf(scur[t1_][1]);                                \
            const float e12 = __expf(scur[t1_][2]);                                \
            const float e13 = __expf(scur[t1_][3]);                                \
            li0 += e00 + e01 + e10 + e11;                                          \
            li1 += e02 + e03 + e12 + e13;                                          \
            uint32_t pah[4];                                                       \
            pah[0] = pack_h2(e00, e01);                                            \
            pah[1] = pack_h2(e02, e03);                                            \
            pah[2] = pack_h2(e10, e11);                                            \
            pah[3] = pack_h2(e12, e13);                                            \
            _Pragma("unroll")                                                      \
            for (int cg = 0; cg < 16; cg++) {                                      \
                uint32_t vf[4];                                                    \
                ldm4(vf, vbase_ + (uint32_t)((cg * 16 + brow) * FV_STRIDE + bkoff) * 2 + kt * 32); \
                mma16816h(o[cg * 2 + 0], pah, vf[0], vf[1]);                       \
                mma16816h(o[cg * 2 + 1], pah, vf[2], vf[3]);                       \
            }                                                                      \
            if (DO_S) {                                                            \
                _Pragma("unroll")                                                  \
                for (int ks2 = 0; ks2 < 4; ks2++) {                                \
                    const int ks_ = (kt * 4 + ks2) * 16;                           \
                    uint32_t qf[4];                                                \
                    ldm4(qf, qbase + ks_ * 2);                                     \
                    _Pragma("unroll")                                              \
                    for (int g_ = 0; g_ < 4; g_++) {                               \
                        uint32_t kf[4];                                            \
                        ldm4(kf, kbase_ + (uint32_t)((g_ * 16 + brow) * FQ_STRIDE + ks_ + bkoff) * 2); \
                        mma16816h(snxt[g_ * 2 + 0], qf, kf[0], kf[1]);             \
                        mma16816h(snxt[g_ * 2 + 1], qf, kf[2], kf[3]);             \
                    }                                                              \
                }                                                                  \
            }                                                                      \
        }                                                                          \
    } while (0)

    #pragma unroll 1
    for (int it2 = 0; it2 < 62; it2 += 2) {
        FLASH_BODY(sa, sbuf, it2, true);
        FLASH_BODY(sbuf, sa, it2 + 1, true);
    }
    FLASH_BODY(sa, sbuf, 62, true);      // PV(62), S(63) -> sbuf
    FLASH_BODY(sbuf, sa, 63, false);     // PV(63) only

    // quad-reduce l, normalize, write Ot fp16
    li0 += __shfl_xor_sync(0xffffffffu, li0, 1);
    li0 += __shfl_xor_sync(0xffffffffu, li0, 2);
    li1 += __shfl_xor_sync(0xffffffffu, li1, 1);
    li1 += __shfl_xor_sync(0xffffffffu, li1, 2);
    const float inv0 = 1.f / li0;
    const float inv1 = 1.f / li1;

    const int r0 = n0 + wid * 16 + (lane >> 2);
    #pragma unroll
    for (int ct = 0; ct < 32; ct++) {
        const int col = ct * 8 + ((lane & 3) << 1);
        __half2 a0, a1;
        a0.x = __float2half_rn(o[ct][0] * inv0);
        a0.y = __float2half_rn(o[ct][1] * inv0);
        a1.x = __float2half_rn(o[ct][2] * inv1);
        a1.y = __float2half_rn(o[ct][3] * inv1);
        *(__half2*)&Ot[boN + (size_t)r0 * CC + col] = a0;
        *(__half2*)&Ot[boN + (size_t)(r0 + 8) * CC + col] = a1;
    }
}

// ---------------- launch ----------------
extern "C" void kernel_launch(void* const* d_in, const int* in_sizes, int n_in,
                              void* d_out, int out_size) {
    const float* input = (const float*)d_in[0];
    const float* gns   = (const float*)d_in[1];
    const float* gnb   = (const float*)d_in[2];
    const float* Wq    = (const float*)d_in[3];
    const float* bq    = (const float*)d_in[4];
    const float* Wk    = (const float*)d_in[5];
    const float* bk    = (const float*)d_in[6];
    const float* Wv    = (const float*)d_in[7];
    const float* bv    = (const float*)d_in[8];
    const float* Wo    = (const float*)d_in[9];
    const float* bo    = (const float*)d_in[10];
    float* out = (float*)d_out;

    __half *hth, *wqk, *wv, *wo, *qk16, *v16, *ot16;
    float* bqk;
    cudaGetSymbolAddress((void**)&hth, g_ht);
    cudaGetSymbolAddress((void**)&wqk, g_wqk);
    cudaGetSymbolAddress((void**)&wv, g_wv);
    cudaGetSymbolAddress((void**)&wo, g_wo);
    cudaGetSymbolAddress((void**)&bqk, g_bqk);
    cudaGetSymbolAddress((void**)&qk16, g_qk16);
    cudaGetSymbolAddress((void**)&v16, g_v16);
    cudaGetSymbolAddress((void**)&ot16, g_ot16);

    cudaFuncSetAttribute(gemm1h_kernel<1, 2, false>, cudaFuncAttributeMaxDynamicSharedMemorySize, GEMM_SMEM);
    cudaFuncSetAttribute(gemm1h_kernel<1, 1, false>, cudaFuncAttributeMaxDynamicSharedMemorySize, GEMM_SMEM);
    cudaFuncSetAttribute(gemm1h_kernel<0, 1, true>, cudaFuncAttributeMaxDynamicSharedMemorySize, GEMM_SMEM);
    cudaFuncSetAttribute(flash_kernel, cudaFuncAttributeMaxDynamicSharedMemorySize, FLASH_SMEM);

    // 1) GroupNorm stats + all weight converts (one kernel)
    gnstat1_kernel<<<dim3(16, 32), 256>>>(input);
    wsplitall_kernel<<<256, 256>>>(Wq, Wk, Wv, Wo, bq, bk);
    gnstat2_kernel<<<1, 32>>>();

    // 2) fused GN-apply + transpose -> fp16
    dim3 gt(NN / 32, CC / 32, BB);
    tconv_kernel<<<gt, dim3(32, 8)>>>(input, gns, gnb, hth);

    // 3) QK merged projection: qk[b][n][512] = hT . [Wq*s;Wk]^T + [bq*s;bk]
    dim3 gqk(2 * CC / 128, NN / 128, BB);
    gemm1h_kernel<1, 2, false><<<gqk, 256, GEMM_SMEM>>>(
        hth, wqk,
        CC, CC, (size_t)NN * CC, 0,
        nullptr, qk16, 2 * CC, (size_t)NN * 2 * CC, bqk, nullptr, CC, 1.0f);
    //    V projection: v[b][o][m]
    dim3 gv(NN / 128, CC / 128, BB);
    gemm1h_kernel<1, 1, false><<<gv, 256, GEMM_SMEM>>>(
        wv, hth,
        CC, CC, 0, (size_t)NN * CC,
        nullptr, v16, NN, (size_t)CC * NN, bv, nullptr, CC, 1.0f);

    // 4) flash attention (R14 config) -> Ot fp16
    dim3 gfl(NN / 128, BB);
    flash_kernel<<<gfl, 256, FLASH_SMEM>>>(qk16, v16, ot16);

    // 5) final: out = Wo . Ot^T + bo + residual (fp32 out)
    dim3 gf(NN / 128, CC / 128, BB);
    gemm1h_kernel<0, 1, true><<<gf, 256, GEMM_SMEM>>>(
        wo, ot16,
        CC, CC, 0, (size_t)NN * CC,
        out, nullptr, NN, (size_t)CC * NN, bo, input, CC, 1.0f);
}

// round 17
// speedup vs baseline: 1.1886x; 1.0071x over previous
#include <cuda_runtime.h>
#include <cuda_fp16.h>
#include <math_constants.h>
#include <cstdint>

// Problem constants
#define BB 4
#define CC 256
#define NN 4096
#define NG 8
#define CPG 32
#define EPSV 1e-5f
#define ATTN_SCALE 0.0625f  // folded into Wq/bq

// 1-pass gemm smem geometry
#define GROW 40
#define MATB (128 * GROW * 2)     // 10240
#define BUF2 (2 * MATB)           // 20480
#define GEMM_SMEM (2 * BUF2)      // 40960

// flash smem geometry (128-query CTA, 64-key tiles)
#define FQ_STRIDE 264
#define FV_STRIDE 72
#define FQ0 0
#define FK0 67584
#define FK1 (FK0 + 33792)
#define FV0 (FK1 + 33792)
#define FV1 (FV0 + 36864)
#define FLASH_SMEM (FV1 + 36864)  // 208896

// ---------------- static scratch ----------------
__device__ __align__(16) float g_part[512 * 2];              // GN partial sums
__device__ __align__(16) __half g_ht[BB * NN * CC];          // h^T [b][n][c]
__device__ __align__(16) __half g_wqk[2 * CC * CC];          // concat(Wq*scale, Wk)
__device__ __align__(16) __half g_wv[CC * CC];
__device__ __align__(16) __half g_wo[CC * CC];
__device__ __align__(16) float g_bqk[2 * CC];                // concat(bq*scale, bk)
__device__ __align__(16) __half g_qk16[BB * NN * 2 * CC];    // qk^T [b][n][512]
__device__ __align__(16) __half g_v16[BB * CC * NN];         // v [b][o][m]
__device__ __align__(16) __half g_ot16[BB * NN * CC];        // Ot [b][n][c]

// ================= PTX helpers =================
__device__ __forceinline__ uint32_t smem_u32(const void* p) {
    uint32_t a;
    asm("{ .reg .u64 t; cvta.to.shared.u64 t, %1; cvt.u32.u64 %0, t; }" : "=r"(a) : "l"(p));
    return a;
}
__device__ __forceinline__ void ldm4(uint32_t r[4], uint32_t addr) {
    asm volatile("ldmatrix.sync.aligned.m8n8.x4.shared.b16 {%0,%1,%2,%3}, [%4];"
                 : "=r"(r[0]), "=r"(r[1]), "=r"(r[2]), "=r"(r[3]) : "r"(addr));
}
__device__ __forceinline__ void mma16816h(float c[4], const uint32_t a[4],
                                          uint32_t b0, uint32_t b1) {
    asm volatile("mma.sync.aligned.m16n8k16.row.col.f32.f16.f16.f32 "
                 "{%0,%1,%2,%3}, {%4,%5,%6,%7}, {%8,%9}, {%0,%1,%2,%3};"
                 : "+f"(c[0]), "+f"(c[1]), "+f"(c[2]), "+f"(c[3])
                 : "r"(a[0]), "r"(a[1]), "r"(a[2]), "r"(a[3]), "r"(b0), "r"(b1));
}
__device__ __forceinline__ void cpa16(uint32_t dst, const void* src) {
    asm volatile("cp.async.cg.shared.global [%0], [%1], 16;" :: "r"(dst), "l"(src));
}
#define CPA_COMMIT() asm volatile("cp.async.commit_group;" ::: "memory")
#define CPA_WAIT0()  asm volatile("cp.async.wait_group 0;" ::: "memory")
#define CPA_WAIT1()  asm volatile("cp.async.wait_group 1;" ::: "memory")

__device__ __forceinline__ uint32_t pack_h2(float a, float b) {
    __half2 h;
    h.x = __float2half_rn(a);
    h.y = __float2half_rn(b);
    return *(uint32_t*)&h;
}

// ---------------- prep: GN partial sums (blocks 0..511) + weight converts (512..767) ----------------
__global__ void prep_kernel(const float* __restrict__ x,
                            const float* __restrict__ Wq, const float* __restrict__ Wk,
                            const float* __restrict__ Wv, const float* __restrict__ Wo,
                            const float* __restrict__ bq, const float* __restrict__ bk) {
    const int blk = blockIdx.x;
    if (blk < 512) {
        const int bg = blk >> 4;
        const int chunk = blk & 15;
        const float* xp = x + (size_t)bg * (CPG * NN) + chunk * 8192;
        float s = 0.f, ss = 0.f;
        for (int i = threadIdx.x; i < 2048; i += 256) {
            float4 v = ((const float4*)xp)[i];
            s += v.x + v.y + v.z + v.w;
            ss += v.x * v.x + v.y * v.y + v.z * v.z + v.w * v.w;
        }
        __shared__ float rs[256], rq[256];
        rs[threadIdx.x] = s; rq[threadIdx.x] = ss;
        __syncthreads();
        for (int st = 128; st > 0; st >>= 1) {
            if (threadIdx.x < st) { rs[threadIdx.x] += rs[threadIdx.x + st]; rq[threadIdx.x] += rq[threadIdx.x + st]; }
            __syncthreads();
        }
        if (threadIdx.x == 0) {
            g_part[(bg * 16 + chunk) * 2 + 0] = rs[0];
            g_part[(bg * 16 + chunk) * 2 + 1] = rq[0];
        }
    } else {
        const int i = (blk - 512) * 256 + threadIdx.x;  // 0..65535 = CC*CC
        g_wqk[i] = __float2half_rn(Wq[i] * ATTN_SCALE);
        g_wqk[CC * CC + i] = __float2half_rn(Wk[i]);
        g_wv[i] = __float2half_rn(Wv[i]);
        g_wo[i] = __float2half_rn(Wo[i]);
        if (i < CC) g_bqk[i] = bq[i] * ATTN_SCALE;
        else if (i < 2 * CC) g_bqk[i] = bk[i - CC];
    }
}

// ---------------- fused GN-finalize + apply + transpose + fp16 ----------------
__global__ void tconv_kernel(const float* __restrict__ x,
                             const float* __restrict__ sc,
                             const float* __restrict__ bi,
                             __half* __restrict__ dst) {
    __shared__ float t[32][33];
    const int b = blockIdx.z;
    const int n0 = blockIdx.x * 32;
    const int c0 = blockIdx.y * 32;
    const int tx = threadIdx.x, ty = threadIdx.y;  // (32, 8)
    const int bg = b * NG + blockIdx.y;

    // finalize stats inline from partials
    float s = 0.f, ss = 0.f;
    #pragma unroll
    for (int j = 0; j < 16; j++) {
        s += g_part[(bg * 16 + j) * 2 + 0];
        ss += g_part[(bg * 16 + j) * 2 + 1];
    }
    const float Mf = (float)(CPG * NN);
    const float mean = s / Mf;
    const float inv = rsqrtf(ss / Mf - mean * mean + EPSV);

    const float* xs = x + (size_t)b * CC * NN;
    #pragma unroll
    for (int k = 0; k < 4; k++)
        t[ty + 8 * k][tx] = xs[(size_t)(c0 + ty + 8 * k) * NN + n0 + tx];
    __syncthreads();
    const int c = c0 + tx;
    const float a = inv * sc[c];
    const float d = bi[c] - mean * a;
    const size_t base = (size_t)b * NN * CC;
    #pragma unroll
    for (int k = 0; k < 4; k++) {
        const int n = n0 + ty + 8 * k;
        dst[base + (size_t)n * CC + c] = __float2half_rn(t[tx][ty + 8 * k] * a + d);
    }
}

// ============================================================================
// merged QKV projections: grid (6, 32, BB).
//   bx<4: QK tile  qk[b][M0+..][N0+..] = hT . wqk^T + bqk[col]
//   bx>=4: V tile  v[b][M0+..][N0+..] = wv . hT^T + bv[row]
// K=256, fp16 out, 2 CTAs/SM.
// ============================================================================
__global__ __launch_bounds__(256, 2)
void qkv_kernel(const float* __restrict__ bv) {
    extern __shared__ char smem[];
    const uint32_t sb = smem_u32(smem);
    const int tid = threadIdx.x;
    const int lane = tid & 31, wid = tid >> 5;
    const int warpM = wid & 3, warpN = wid >> 2;
    const int bx = blockIdx.x, by = blockIdx.y, bz = blockIdx.z;

    const __half* pA;
    const __half* pB;
    size_t ldA, ldB, ldOut;
    __half* outp;
    const float* bias;
    int biasrow;  // 1: bias[row], 0: bias[col]
    int M0, N0;
    if (bx < 4) {
        M0 = by * 128; N0 = bx * 128;
        pA = g_ht + (size_t)bz * NN * CC + (size_t)M0 * CC; ldA = CC;
        pB = g_wqk + (size_t)N0 * CC; ldB = CC;
        outp = g_qk16 + (size_t)bz * NN * 2 * CC; ldOut = 2 * CC;
        bias = g_bqk; biasrow = 0;
    } else {
        M0 = (bx - 4) * 128; N0 = by * 128;
        pA = g_wv + (size_t)M0 * CC; ldA = CC;
        pB = g_ht + (size_t)bz * NN * CC + (size_t)N0 * CC; ldB = CC;
        outp = g_v16 + (size_t)bz * CC * NN; ldOut = NN;
        bias = bv; biasrow = 1;
    }

    const int ga = lane >> 3;
    const int arow = ((ga & 1) << 3) + (lane & 7);
    const int akoff = (ga >> 1) << 3;
    const int brow = ((ga >> 1) << 3) + (lane & 7);
    const int bkoff = (ga & 1) << 3;

    float acc[2][8][4];
    #pragma unroll
    for (int i = 0; i < 2; i++)
        #pragma unroll
        for (int j = 0; j < 8; j++)
            #pragma unroll
            for (int k = 0; k < 4; k++) acc[i][j][k] = 0.f;

    #define ISSUE_COPY2(bufi, kc) do {                                             \
        _Pragma("unroll")                                                          \
        for (int i_ = 0; i_ < 4; i_++) {                                           \
            int idx_ = tid + i_ * 256;                                             \
            int mat_ = idx_ >> 9;                                                  \
            int r_ = (idx_ >> 2) & 127;                                            \
            int seg_ = idx_ & 3;                                                   \
            const __half* src_ = (mat_ ? pB + (size_t)r_ * ldB : pA + (size_t)r_ * ldA) \
                                 + (kc) + seg_ * 8;                                \
            uint32_t dst_ = sb + (bufi) * BUF2 + mat_ * MATB + (r_ * GROW + seg_ * 8) * 2; \
            cpa16(dst_, src_);                                                     \
        }                                                                          \
        CPA_COMMIT();                                                              \
    } while (0)

    ISSUE_COPY2(0, 0);

    for (int c = 0; c < 8; c++) {
        if (c + 1 < 8) {
            ISSUE_COPY2((c + 1) & 1, (c + 1) << 5);
            CPA_WAIT1();
        } else {
            CPA_WAIT0();
        }
        __syncthreads();

        const uint32_t bufb = sb + (c & 1) * BUF2;
        #pragma unroll
        for (int ks = 0; ks < 32; ks += 16) {
            uint32_t ah[2][4];
            #pragma unroll
            for (int mt = 0; mt < 2; mt++) {
                uint32_t off = (uint32_t)(((warpM * 32 + mt * 16 + arow) * GROW + ks + akoff) * 2);
                ldm4(ah[mt], bufb + off);
            }
            uint32_t bh[4][4];
            #pragma unroll
            for (int ng = 0; ng < 4; ng++) {
                uint32_t off = (uint32_t)(((warpN * 64 + ng * 16 + brow) * GROW + ks + bkoff) * 2);
                ldm4(bh[ng], bufb + MATB + off);
            }
            #pragma unroll
            for (int mt = 0; mt < 2; mt++)
                #pragma unroll
                for (int ng = 0; ng < 4; ng++)
                    #pragma unroll
                    for (int h = 0; h < 2; h++)
                        mma16816h(acc[mt][ng * 2 + h], ah[mt], bh[ng][h * 2], bh[ng][h * 2 + 1]);
        }
        __syncthreads();
    }

    #pragma unroll
    for (int mt = 0; mt < 2; mt++)
        #pragma unroll
        for (int nt = 0; nt < 8; nt++) {
            const int row0 = M0 + warpM * 32 + mt * 16 + (lane >> 2);
            const int col = N0 + warpN * 64 + nt * 8 + ((lane & 3) << 1);
            #pragma unroll
            for (int rr = 0; rr < 2; rr++) {
                const int r = row0 + rr * 8;
                float v0 = acc[mt][nt][rr * 2 + 0];
                float v1 = acc[mt][nt][rr * 2 + 1];
                if (biasrow) { const float bb = bias[r]; v0 += bb; v1 += bb; }
                else { v0 += bias[col]; v1 += bias[col + 1]; }
                __half2 hp;
                hp.x = __float2half_rn(v0);
                hp.y = __float2half_rn(v1);
                *(__half2*)&outp[(size_t)r * ldOut + col] = hp;
            }
        }
}

// ============================================================================
// final projection: out = Wo . Ot^T + bo + residual (fp32 out), 2 CTAs/SM
// ============================================================================
__global__ __launch_bounds__(256, 2)
void finproj_kernel(const __half* __restrict__ Ah, const __half* __restrict__ Bh,
                    float* __restrict__ OutF,
                    const float* __restrict__ bias, const float* __restrict__ res) {
    extern __shared__ char smem[];
    const uint32_t sb = smem_u32(smem);
    const int tid = threadIdx.x;
    const int lane = tid & 31, wid = tid >> 5;
    const int warpM = wid & 3, warpN = wid >> 2;
    const int bz = blockIdx.z;
    const int N0 = blockIdx.x * 128;
    const int M0 = blockIdx.y * 128;

    const __half* pA = Ah + (size_t)M0 * CC;                       // Wo rows
    const __half* pB = Bh + (size_t)bz * NN * CC + (size_t)N0 * CC; // Ot rows
    const size_t ldA = CC, ldB = CC;

    const int ga = lane >> 3;
    const int arow = ((ga & 1) << 3) + (lane & 7);
    const int akoff = (ga >> 1) << 3;
    const int brow = ((ga >> 1) << 3) + (lane & 7);
    const int bkoff = (ga & 1) << 3;

    float acc[2][8][4];
    #pragma unroll
    for (int i = 0; i < 2; i++)
        #pragma unroll
        for (int j = 0; j < 8; j++)
            #pragma unroll
            for (int k = 0; k < 4; k++) acc[i][j][k] = 0.f;

    ISSUE_COPY2(0, 0);

    for (int c = 0; c < 8; c++) {
        if (c + 1 < 8) {
            ISSUE_COPY2((c + 1) & 1, (c + 1) << 5);
            CPA_WAIT1();
        } else {
            CPA_WAIT0();
        }
        __syncthreads();

        const uint32_t bufb = sb + (c & 1) * BUF2;
        #pragma unroll
        for (int ks = 0; ks < 32; ks += 16) {
            uint32_t ah[2][4];
            #pragma unroll
            for (int mt = 0; mt < 2; mt++) {
                uint32_t off = (uint32_t)(((warpM * 32 + mt * 16 + arow) * GROW + ks + akoff) * 2);
                ldm4(ah[mt], bufb + off);
            }
            uint32_t bh[4][4];
            #pragma unroll
            for (int ng = 0; ng < 4; ng++) {
                uint32_t off = (uint32_t)(((warpN * 64 + ng * 16 + brow) * GROW + ks + bkoff) * 2);
                ldm4(bh[ng], bufb + MATB + off);
            }
            #pragma unroll
            for (int mt = 0; mt < 2; mt++)
                #pragma unroll
                for (int ng = 0; ng < 4; ng++)
                    #pragma unroll
                    for (int h = 0; h < 2; h++)
                        mma16816h(acc[mt][ng * 2 + h], ah[mt], bh[ng][h * 2], bh[ng][h * 2 + 1]);
        }
        __syncthreads();
    }

    #pragma unroll
    for (int mt = 0; mt < 2; mt++)
        #pragma unroll
        for (int nt = 0; nt < 8; nt++) {
            const int row0 = M0 + warpM * 32 + mt * 16 + (lane >> 2);
            const int col = N0 + warpN * 64 + nt * 8 + ((lane & 3) << 1);
            #pragma unroll
            for (int rr = 0; rr < 2; rr++) {
                const int r = row0 + rr * 8;
                const float bb = bias[r];
                const size_t off = (size_t)bz * CC * NN + (size_t)r * NN + col;
                float2 o;
                o.x = acc[mt][nt][rr * 2 + 0] + bb + res[off];
                o.y = acc[mt][nt][rr * 2 + 1] + bb + res[off + 1];
                *(float2*)&OutF[off] = o;
            }
        }
}

// ============================================================================
// Flash attention (R14/R16 config, unchanged): 128-query CTA, 64-key tiles,
// pipelined S, max-free softmax.
// ============================================================================
__global__ __launch_bounds__(256, 1)
void flash_kernel(const __half* __restrict__ QK, const __half* __restrict__ Vh,
                  __half* __restrict__ Ot) {
    extern __shared__ char smem[];
    const uint32_t sb = smem_u32(smem);
    const int tid = threadIdx.x;
    const int lane = tid & 31, wid = tid >> 5;
    const int b = blockIdx.y;
    const int n0 = blockIdx.x * 128;

    const __half* qh = QK + (size_t)b * NN * 512;
    const __half* kh = qh + 256;
    const __half* vh = Vh + (size_t)b * CC * NN;
    const size_t boN = (size_t)b * NN * CC;

    const uint32_t fkb[2] = { sb + FK0, sb + FK1 };
    const uint32_t fvb[2] = { sb + FV0, sb + FV1 };

    #define LOAD_K(bufi, mm0) do {                                                 \
        for (int i = tid; i < 2048; i += 256) {                                    \
            const int r_ = i >> 5, seg_ = i & 31;                                  \
            cpa16(fkb[bufi] + r_ * 528 + seg_ * 16,                                \
                  kh + (size_t)((mm0) + r_) * 512 + seg_ * 8);                     \
        }                                                                          \
    } while (0)
    #define LOAD_V(bufi, mm0) do {                                                 \
        for (int i = tid; i < 2048; i += 256) {                                    \
            const int r_ = i >> 3, seg_ = i & 7;                                   \
            cpa16(fvb[bufi] + r_ * 144 + seg_ * 16,                                \
                  vh + (size_t)r_ * NN + (mm0) + seg_ * 8);                        \
        }                                                                          \
    } while (0)

    // prologue group 0: Q + K(0)
    for (int i = tid; i < 128 * 32; i += 256) {
        const int r = i >> 5, seg = i & 31;
        cpa16(sb + FQ0 + r * 528 + seg * 16, qh + (size_t)(n0 + r) * 512 + seg * 8);
    }
    LOAD_K(0, 0);
    CPA_COMMIT();
    // prologue group 1: K(1) + V(0)
    LOAD_K(1, 64);
    LOAD_V(0, 0);
    CPA_COMMIT();

    const int ga = lane >> 3;
    const int arow = ((ga & 1) << 3) + (lane & 7);
    const int akoff = (ga >> 1) << 3;
    const int brow = ((ga >> 1) << 3) + (lane & 7);
    const int bkoff = (ga & 1) << 3;

    float o[32][4];
    #pragma unroll
    for (int i = 0; i < 32; i++)
        #pragma unroll
        for (int j = 0; j < 4; j++) o[i][j] = 0.f;
    float li0 = 0.f, li1 = 0.f;
    float sa[8][4], sbuf[8][4];

    const uint32_t qbase = sb + FQ0 + (uint32_t)((wid * 16 + arow) * FQ_STRIDE + akoff) * 2;

    CPA_WAIT0();
    __syncthreads();

    // ---- prologue: S(0) into sa ----
    #pragma unroll
    for (int t = 0; t < 8; t++)
        #pragma unroll
        for (int e = 0; e < 4; e++) sa[t][e] = 0.f;
    #pragma unroll
    for (int ks = 0; ks < 256; ks += 16) {
        uint32_t qf[4];
        ldm4(qf, qbase + ks * 2);
        #pragma unroll
        for (int g = 0; g < 4; g++) {
            uint32_t kf[4];
            ldm4(kf, fkb[0] + (uint32_t)((g * 16 + brow) * FQ_STRIDE + ks + bkoff) * 2);
            mma16816h(sa[g * 2 + 0], qf, kf[0], kf[1]);
            mma16816h(sa[g * 2 + 1], qf, kf[2], kf[3]);
        }
    }

    #define FLASH_BODY(scur, snxt, it, DO_S) do {                                  \
        CPA_WAIT0();                                                               \
        __syncthreads();                                                           \
        if ((it) + 2 < 64) LOAD_K((it) & 1, ((it) + 2) * 64);                      \
        if ((it) + 1 < 64) LOAD_V(((it) + 1) & 1, ((it) + 1) * 64);                \
        CPA_COMMIT();                                                              \
        const uint32_t vbase_ = fvb[(it) & 1];                                     \
        const uint32_t kbase_ = fkb[((it) + 1) & 1];                               \
        if (DO_S) {                                                                \
            _Pragma("unroll")                                                      \
            for (int t_ = 0; t_ < 8; t_++)                                         \
                _Pragma("unroll")                                                  \
                for (int e_ = 0; e_ < 4; e_++) snxt[t_][e_] = 0.f;                 \
        }                                                                          \
        _Pragma("unroll")                                                          \
        for (int kt = 0; kt < 4; kt++) {                                           \
            const int t0_ = kt * 2, t1_ = t0_ + 1;                                 \
            const float e00 = __expf(scur[t0_][0]);                                \
            const float e01 = __expf(scur[t0_][1]);                                \
            const float e02 = __expf(scur[t0_][2]);                                \
            const float e03 = __expf(scur[t0_][3]);                                \
            const float e10 = __expf(scur[t1_][0]);                                \
            const float e11 = __expf(scur[t1_][1]);                                \
            const float e12 = __expf(scur[t1_][2]);                                \
            const float e13 = __expf(scur[t1_][3]);                                \
            li0 += e00 + e01 + e10 + e11;                                          \
            li1 += e02 + e03 + e12 + e13;                                          \
            uint32_t pah[4];                                                       \
            pah[0] = pack_h2(e00, e01);                                            \
            pah[1] = pack_h2(e02, e03);                                            \
            pah[2] = pack_h2(e10, e11);                                            \
            pah[3] = pack_h2(e12, e13);                                            \
            _Pragma("unroll")                                                      \
            for (int cg = 0; cg < 16; cg++) {                                      \
                uint32_t vf[4];                                                    \
                ldm4(vf, vbase_ + (uint32_t)((cg * 16 + brow) * FV_STRIDE + bkoff) * 2 + kt * 32); \
                mma16816h(o[cg * 2 + 0], pah, vf[0], vf[1]);                       \
                mma16816h(o[cg * 2 + 1], pah, vf[2], vf[3]);                       \
            }                                                                      \
            if (DO_S) {                                                            \
                _Pragma("unroll")                                                  \
                for (int ks2 = 0; ks2 < 4; ks2++) {                                \
                    const int ks_ = (kt * 4 + ks2) * 16;                           \
                    uint32_t qf[4];                                                \
                    ldm4(qf, qbase + ks_ * 2);                                     \
                    _Pragma("unroll")                                              \
                    for (int g_ = 0; g_ < 4; g_++) {                               \
                        uint32_t kf[4];                                            \
                        ldm4(kf, kbase_ + (uint32_t)((g_ * 16 + brow) * FQ_STRIDE + ks_ + bkoff) * 2); \
                        mma16816h(snxt[g_ * 2 + 0], qf, kf[0], kf[1]);             \
                        mma16816h(snxt[g_ * 2 + 1], qf, kf[2], kf[3]);             \
                    }                                                              \
                }                                                                  \
            }                                                                      \
        }                                                                          \
    } while (0)

    #pragma unroll 1
    for (int it2 = 0; it2 < 62; it2 += 2) {
        FLASH_BODY(sa, sbuf, it2, true);
        FLASH_BODY(sbuf, sa, it2 + 1, true);
    }
    FLASH_BODY(sa, sbuf, 62, true);
    FLASH_BODY(sbuf, sa, 63, false);

    // quad-reduce l, normalize, write Ot fp16
    li0 += __shfl_xor_sync(0xffffffffu, li0, 1);
    li0 += __shfl_xor_sync(0xffffffffu, li0, 2);
    li1 += __shfl_xor_sync(0xffffffffu, li1, 1);
    li1 += __shfl_xor_sync(0xffffffffu, li1, 2);
    const float inv0 = 1.f / li0;
    const float inv1 = 1.f / li1;

    const int r0 = n0 + wid * 16 + (lane >> 2);
    #pragma unroll
    for (int ct = 0; ct < 32; ct++) {
        const int col = ct * 8 + ((lane & 3) << 1);
        __half2 a0, a1;
        a0.x = __float2half_rn(o[ct][0] * inv0);
        a0.y = __float2half_rn(o[ct][1] * inv0);
        a1.x = __float2half_rn(o[ct][2] * inv1);
        a1.y = __float2half_rn(o[ct][3] * inv1);
        *(__half2*)&Ot[boN + (size_t)r0 * CC + col] = a0;
        *(__half2*)&Ot[boN + (size_t)(r0 + 8) * CC + col] = a1;
    }
}

// ---------------- launch ----------------
extern "C" void kernel_launch(void* const* d_in, const int* in_sizes, int n_in,
                              void* d_out, int out_size) {
    const float* input = (const float*)d_in[0];
    const float* gns   = (const float*)d_in[1];
    const float* gnb   = (const float*)d_in[2];
    const float* Wq    = (const float*)d_in[3];
    const float* bq    = (const float*)d_in[4];
    const float* Wk    = (const float*)d_in[5];
    const float* bk    = (const float*)d_in[6];
    const float* Wv    = (const float*)d_in[7];
    const float* bv    = (const float*)d_in[8];
    const float* Wo    = (const float*)d_in[9];
    const float* bo    = (const float*)d_in[10];
    float* out = (float*)d_out;

    __half *hth, *wo, *qk16, *v16, *ot16;
    cudaGetSymbolAddress((void**)&hth, g_ht);
    cudaGetSymbolAddress((void**)&wo, g_wo);
    cudaGetSymbolAddress((void**)&qk16, g_qk16);
    cudaGetSymbolAddress((void**)&v16, g_v16);
    cudaGetSymbolAddress((void**)&ot16, g_ot16);

    cudaFuncSetAttribute(qkv_kernel, cudaFuncAttributeMaxDynamicSharedMemorySize, GEMM_SMEM);
    cudaFuncSetAttribute(finproj_kernel, cudaFuncAttributeMaxDynamicSharedMemorySize, GEMM_SMEM);
    cudaFuncSetAttribute(flash_kernel, cudaFuncAttributeMaxDynamicSharedMemorySize, FLASH_SMEM);

    // 1) GN partial sums + all weight converts (one kernel)
    prep_kernel<<<768, 256>>>(input, Wq, Wk, Wv, Wo, bq, bk);

    // 2) fused GN-finalize + apply + transpose -> fp16
    dim3 gt(NN / 32, CC / 32, BB);
    tconv_kernel<<<gt, dim3(32, 8)>>>(input, gns, gnb, hth);

    // 3) merged QK + V projections (one launch)
    dim3 gqkv(6, 32, BB);
    qkv_kernel<<<gqkv, 256, GEMM_SMEM>>>(bv);

    // 4) flash attention -> Ot fp16
    dim3 gfl(NN / 128, BB);
    flash_kernel<<<gfl, 256, FLASH_SMEM>>>(qk16, v16, ot16);

    // 5) final projection + residual
    dim3 gf(NN / 128, CC / 128, BB);
    finproj_kernel<<<gf, 256, GEMM_SMEM>>>(wo, ot16, out, bo, input);
}